// round 16
// baseline (speedup 1.0000x reference)
#include <cuda_runtime.h>
#include <cuda_fp16.h>
#include <math.h>
#include <cstdint>

// ===========================================================================
// Problem constants
// ===========================================================================
#define Bc   16
#define Tc   16
#define Hc   161
#define Wc   181
#define HWc  (Hc*Wc)            // 29141
#define Fc   21
#define F4c  84

// Tile: M = 384 pixels (96 wide x 4 high), N = 88, K = 240 (single fp16 pass)
// 24 warps: warp = m32 x n44 (4my x 3mx x 2nhalf)
#define TILE_W 96
#define TILE_H 4
#define NTX 2
#define NTY 41
#define NTILES (NTX*NTY*Bc)     // 1312
#define GRID 148

// B matrix: n-major [88][248] fp16 (row 496 B, k pad zero)
#define BROW   248
#define B_TOTAL_B (88*BROW*2)       // 43,648

// Halo: channel-last [6 rows][98 cols][24 ch] fp16
#define HROWS 6
#define HCOLS 98
#define HCH   24
#define HPLANE_B (HROWS*HCOLS*HCH*2)   // 28,224 per halo buffer

// c tile in smem: [21 co][4 rows][96 px] f32
#define CTILE_B (Fc*TILE_H*TILE_W*4)   // 32,256

// SMEM layout
#define SM_B     0
#define SM_BIAS  B_TOTAL_B                      // 43,648
#define SM_HALO0 (SM_BIAS + 352)                // 44,000 (16B aligned)
#define SM_HALO1 (SM_HALO0 + HPLANE_B)          // 72,224
#define SM_C0    (SM_HALO1 + HPLANE_B + 32)     // 100,480 (32B zero pad before)
#define SM_C1    (SM_C0 + CTILE_B)              // 132,736
#define SMEM_BYTES (SM_C1 + CTILE_B)            // 164,992

#define NTHR 768

// Combined input arrays: [b][HW][24] ch-last; ch 0..20 = h, ch 21..23 = x(t)
#define ASZ (Bc*HWc*24)
#define XSZ (Bc*Tc*3*HWc)
// Padded c layout: [b][41 ty][21 co][4 rows][192 px] f32
#define CROWP 192
#define CSZP (Bc*NTY*Fc*TILE_H*CROWP)

// ===========================================================================
// Device globals
// ===========================================================================
__device__ __half g_B[88*BROW];
__device__ __align__(16) __half g_A0[ASZ];  // read at even t
__device__ __align__(16) __half g_A1[ASZ];  // read at odd t
__device__ __align__(16) float g_c[CSZP];   // padded tile layout
__device__ __half g_x[XSZ];                 // planar x fp16
__device__ unsigned g_bar;                  // grid barrier counter

// ===========================================================================
// PTX helpers (compute_103-safe)
// ===========================================================================
__device__ __forceinline__ uint32_t smem_to_u32(const void* p) {
    uint32_t a;
    asm("{ .reg .u64 t; cvta.to.shared.u64 t, %1; cvt.u32.u64 %0, t; }"
        : "=r"(a) : "l"(p));
    return a;
}
#define LDSM_X4(r0,r1,r2,r3,addr) \
    asm volatile("ldmatrix.sync.aligned.m8n8.x4.shared.b16 {%0,%1,%2,%3}, [%4];" \
        : "=r"(r0),"=r"(r1),"=r"(r2),"=r"(r3) : "r"(addr))
#define LDSM_X2(r0,r1,addr) \
    asm volatile("ldmatrix.sync.aligned.m8n8.x2.shared.b16 {%0,%1}, [%2];" \
        : "=r"(r0),"=r"(r1) : "r"(addr))
#define MMA_F32(d,a0,a1,a2,a3,b0,b1) \
    asm volatile("mma.sync.aligned.m16n8k16.row.col.f32.f16.f16.f32 " \
        "{%0,%1,%2,%3}, {%4,%5,%6,%7}, {%8,%9}, {%0,%1,%2,%3};" \
        : "+f"((d)[0]),"+f"((d)[1]),"+f"((d)[2]),"+f"((d)[3]) \
        : "r"(a0),"r"(a1),"r"(a2),"r"(a3),"r"(b0),"r"(b1))
// L2-only async copy (no L1 caching -> safe across grid-barrier steps)
#define CP_ASYNC16(dst, src, sz) \
    asm volatile("cp.async.cg.shared.global [%0], [%1], 16, %2;" \
        :: "r"(dst), "l"(src), "r"(sz) : "memory")
#define CP_COMMIT() asm volatile("cp.async.commit_group;" ::: "memory")
#define CP_WAIT0()  asm volatile("cp.async.wait_group 0;" ::: "memory")

__device__ __forceinline__ float hsig(float v) {
    return fminf(fmaxf(0.2f*v + 0.5f, 0.0f), 1.0f);
}
// fast accurate tanh: 1 - 2/(exp(2x)+1). 2 MUFU + few FMA, rel err ~1e-6.
__device__ __forceinline__ float tanh_fast(float x) {
    float e = __expf(2.0f*x);
    return 1.0f - __fdividef(2.0f, e + 1.0f);
}

// ===========================================================================
// Aux kernels
// ===========================================================================
__global__ void init_kernel(const float* __restrict__ x) {
    if (blockIdx.x == 0 && threadIdx.x == 0) g_bar = 0u;
    for (int i = blockIdx.x*blockDim.x + threadIdx.x; i < ASZ; i += gridDim.x*blockDim.x) {
        int ch = i % 24;
        int p  = (i / 24) % HWc;
        int b  = i / (24*HWc);
        __half v = __float2half_rn(0.0f);
        if (ch >= 21)
            v = __float2half_rn(x[(((size_t)(b*Tc)*HWc) + p)*3 + (ch - 21)]);
        g_A0[i] = v;
    }
    for (int i = blockIdx.x*blockDim.x + threadIdx.x; i < CSZP; i += gridDim.x*blockDim.x)
        g_c[i] = 0.0f;
}

__global__ void xsplit_kernel(const float* __restrict__ x) {
    for (int i = blockIdx.x*blockDim.x + threadIdx.x; i < XSZ; i += gridDim.x*blockDim.x) {
        int p  = i % HWc;
        int r  = i / HWc;
        int c  = r % 3;
        int bt = r / 3;
        g_x[i] = __float2half_rn(x[((size_t)bt*HWc + p)*3 + c]);
    }
}

// Pack weights: B[n][k], n = 4*co+g, k = dy*80 + dx*24 + cin
// cin: 0..20 = h (rkern), 21..23 = x (kern); k%80>=72 and k>=240 zero pad
__global__ void packB_kernel(const float* __restrict__ kern, const float* __restrict__ rkern) {
    int i = blockIdx.x*blockDim.x + threadIdx.x;
    const int TOT = 88*BROW;
    if (i >= TOT) return;
    int n    = i / BROW;
    int k    = i - n*BROW;
    int co = n >> 2, g = n & 3;
    float w = 0.0f;
    if (k < 240 && co < Fc) {
        int dy = k / 80, r2 = k - dy*80;
        if (r2 < 72) {
            int dx = r2 / 24, cin = r2 - dx*24;
            int col = g*Fc + co;
            if (cin < 21) w = rkern[((dy*3 + dx)*Fc + cin     )*F4c + col];
            else          w = kern [((dy*3 + dx)*3  + (cin-21))*F4c + col];
        }
    }
    g_B[i] = __float2half_rn(w);
}

// ===========================================================================
// Fused persistent kernel: all 16 timesteps, grid barrier between steps
// ===========================================================================
__device__ __forceinline__ void prefetch_halo(
    uint32_t dstbase, int b, int x0, int y0,
    const __half* __restrict__ A, int tid) {
    const int TOTE = HROWS*HCOLS;     // 588 pixel-entries
    for (int i = tid; i < TOTE; i += NTHR) {
        int c = i % HCOLS;
        int r = i / HCOLS;
        int gy = y0 + r - 1, gx = x0 + c - 1;
        bool ok = ((unsigned)gy < (unsigned)Hc) && ((unsigned)gx < (unsigned)Wc);
        size_t off = ok ? ((size_t)b*HWc + (size_t)gy*Wc + gx)*24 : 0;
        const __half* src = A + off;
        uint32_t dst = dstbase + (uint32_t)(r*HCOLS + c)*48;
        uint32_t sz = ok ? 16u : 0u;
        #pragma unroll
        for (int q = 0; q < 3; q++)
            CP_ASYNC16(dst + q*16, src + q*8, sz);
    }
}

__device__ __forceinline__ void prefetch_c(
    uint32_t dstbase, int b, int ty, int x0, int tid) {
    const int TOTC = Fc*TILE_H*24;    // 2016 16B chunks
    const float* cbase = g_c + ((size_t)(b*NTY + ty)*Fc)*TILE_H*CROWP + x0;
    for (int i = tid; i < TOTC; i += NTHR) {
        int ch16 = i % 24;
        int row  = (i / 24) & 3;
        int co   = i / 96;
        const float* src = cbase + (size_t)(co*TILE_H + row)*CROWP + ch16*4;
        uint32_t dst = dstbase + (uint32_t)((co*TILE_H + row)*TILE_W + ch16*4)*4;
        CP_ASYNC16(dst, src, 16u);
    }
}

__global__ __launch_bounds__(NTHR, 1)
void step_all_kernel(const float* __restrict__ bias) {
    extern __shared__ unsigned char smem[];
    const uint32_t sbase = smem_to_u32(smem);
    const int tid  = threadIdx.x;
    const int w    = tid >> 5;
    const int lane = tid & 31;

    // ---- Stage B + bias ONCE; zero overread pads ----
    {
        const float4* gB = reinterpret_cast<const float4*>(g_B);
        float4* sB = reinterpret_cast<float4*>(smem + SM_B);
        #pragma unroll 4
        for (int i = tid; i < B_TOTAL_B/16; i += NTHR) sB[i] = gB[i];
        if (tid < 88) {
            int co = tid >> 2, g = tid & 3;
            reinterpret_cast<float*>(smem + SM_BIAS)[tid] =
                (co < Fc) ? bias[g*Fc + co] : 0.0f;
        }
        if (tid < 8)
            reinterpret_cast<uint32_t*>(smem + SM_HALO1 + HPLANE_B)[tid] = 0;
        if (tid >= 8 && tid < 16)
            reinterpret_cast<uint32_t*>(smem + SM_HALO1)[tid - 8] = 0;
    }
    __syncthreads();

    // ---- Warp tiling: 24 warps = 4my x 3mx x 2nhalf, warp tile m32 x n44 ----
    const int nhalf = w & 1;
    const int mx    = (w >> 1) % 3;
    const int my    = w / 6;
    const int mxb   = mx * 32;
    const int NF    = nhalf ? 5 : 6;
    const uint32_t aLane  = (uint32_t)(lane & 15)*48 + (uint32_t)((lane >> 4) & 1)*16;
    const uint32_t bLane4 = (uint32_t)(lane & 7)*496 + (uint32_t)((lane >> 3) & 1)*16
                          + (uint32_t)((lane >> 4) & 1)*(8*496);
    const uint32_t bLane2 = (uint32_t)(lane & 7)*496 + (uint32_t)((lane >> 3) & 1)*16;
    const uint32_t nOff   = (uint32_t)nhalf * (48*496);
    const float* sb_all = reinterpret_cast<const float*>(smem + SM_BIAS);

    #pragma unroll 1
    for (int t = 0; t < Tc; t++) {
        const __half* Ain  = (t & 1) ? g_A1 : g_A0;
        __half*       Aout = (t & 1) ? g_A0 : g_A1;

        // ---- Prologue: prefetch this CTA's first tile (halo + c) ----
        int idx = blockIdx.x;
        if (idx < NTILES) {
            int b0 = idx / (NTX*NTY), r0 = idx % (NTX*NTY);
            prefetch_halo(sbase + SM_HALO0, b0, (r0 & 1)*TILE_W, (r0 >> 1)*TILE_H,
                          Ain, tid);
            prefetch_c(sbase + SM_C0, b0, r0 >> 1, (r0 & 1)*TILE_W, tid);
        }
        CP_COMMIT();

        int cur = 0;
        for (; idx < NTILES; idx += GRID) {
            CP_WAIT0();
            __syncthreads();

            int nxt = idx + GRID;
            if (nxt < NTILES) {
                int bn = nxt / (NTX*NTY), rn = nxt % (NTX*NTY);
                prefetch_halo(sbase + (cur ? SM_HALO0 : SM_HALO1),
                              bn, (rn & 1)*TILE_W, (rn >> 1)*TILE_H, Ain, tid);
                prefetch_c(sbase + (cur ? SM_C0 : SM_C1),
                           bn, rn >> 1, (rn & 1)*TILE_W, tid);
            }
            CP_COMMIT();

            const int b  = idx / (NTX*NTY);
            const int rr = idx % (NTX*NTY);
            const int x0 = (rr & 1)*TILE_W;
            const int ty = rr >> 1;
            const int y0 = ty*TILE_H;
            const uint32_t Hbuf = sbase + (cur ? SM_HALO1 : SM_HALO0);
            float* Cs = reinterpret_cast<float*>(smem + (cur ? SM_C1 : SM_C0));

            // ---- Mainloop: single pass, f32 accum ----
            float d[2][6][4];
            #pragma unroll
            for (int mf = 0; mf < 2; mf++)
                #pragma unroll
                for (int nf = 0; nf < 6; nf++)
                    #pragma unroll
                    for (int q = 0; q < 4; q++) d[mf][nf][q] = 0.0f;

            {
                const uint32_t Bb = sbase + SM_B + nOff;
                #pragma unroll 1
                for (int dy = 0; dy < 3; dy++) {
                    const uint32_t Arow = Hbuf + (uint32_t)((my + dy)*HCOLS + mxb)*48 + aLane;
                    const uint32_t Brow = Bb + (uint32_t)dy*160;
                    #pragma unroll
                    for (int c = 0; c < 5; c++) {
                        uint32_t bq[12];
                        {
                            const uint32_t ba4 = Brow + bLane4 + c*32;
                            LDSM_X4(bq[0], bq[1], bq[2], bq[3], ba4);
                            LDSM_X4(bq[4], bq[5], bq[6], bq[7], ba4 + 2*(8*496));
                            if (nhalf) {
                                LDSM_X2(bq[8], bq[9], Brow + bLane2 + 4*(8*496) + c*32);
                            } else {
                                LDSM_X4(bq[8], bq[9], bq[10], bq[11], ba4 + 4*(8*496));
                            }
                        }
                        #pragma unroll
                        for (int mf = 0; mf < 2; mf++) {
                            uint32_t a0, a1, a2, a3;
                            LDSM_X4(a0, a1, a2, a3, Arow + mf*(16*48) + c*32);
                            #pragma unroll
                            for (int nf = 0; nf < 6; nf++)
                                if (nf < NF)
                                    MMA_F32(d[mf][nf], a0, a1, a2, a3, bq[2*nf], bq[2*nf+1]);
                        }
                    }
                }
            }

            // ---- Epilogue: gate update, c from smem, write h to Aout ----
            {
                const int gid    = lane >> 2;
                const int co_off = (lane >> 1) & 1;
                const bool lowrow = ((lane & 1) == 0);
                const int gy = y0 + my;
                const int cob = nhalf * 12;
                float* cg_tile = g_c + ((size_t)(b*NTY + ty)*Fc)*TILE_H*CROWP;
                #pragma unroll
                for (int mf = 0; mf < 2; mf++) {
                    #pragma unroll
                    for (int nf = 0; nf < 6; nf++) {
                        if (nf >= NF) continue;
                        float* dd = d[mf][nf];
                        float r0 = __shfl_xor_sync(0xFFFFFFFFu, dd[0], 1);
                        float r1 = __shfl_xor_sync(0xFFFFFFFFu, dd[1], 1);
                        float r2 = __shfl_xor_sync(0xFFFFFFFFu, dd[2], 1);
                        float r3 = __shfl_xor_sync(0xFFFFFFFFu, dd[3], 1);
                        float zi, zf, zg, zo;
                        int rowm;
                        if (lowrow) { zi = dd[0]; zf = dd[1]; zg = r0;    zo = r1;    rowm = gid; }
                        else        { zi = r2;    zf = r3;    zg = dd[2]; zo = dd[3]; rowm = gid + 8; }
                        const int co = cob + 2*nf + co_off;
                        const int lx = mxb + mf*16 + rowm;      // 0..95
                        const int gx = x0 + lx;
                        if (co < Fc && gx < Wc && gy < Hc) {
                            const float* sb = sb_all + co*4;
                            float ig = hsig(zi + sb[0]);
                            float fg = hsig(zf + sb[1]);
                            float gg = tanh_fast(zg + sb[2]);
                            float og = hsig(zo + sb[3]);
                            float cold = Cs[(co*TILE_H + my)*TILE_W + lx];
                            float cn = fg * cold + ig * gg;
                            cg_tile[(size_t)(co*TILE_H + my)*CROWP + gx] = cn;
                            float h = og * tanh_fast(cn);
                            size_t pix = (size_t)gy*Wc + gx;
                            Aout[((size_t)b*HWc + pix)*24 + co] = __float2half_rn(h);
                        }
                    }
                }
                // x-forwarding: nhalf==1 warps write x(t+1) into slots 21..23
                if (nhalf) {
                    const int t1 = t + 1;
                    const int gy2 = y0 + my;
                    for (int j = lane; j < 32*3; j += 32) {
                        int pxl = j / 3, ch = j - 3*pxl;
                        int gx = x0 + mxb + pxl;
                        if (gx < Wc && gy2 < Hc) {
                            size_t pix = (size_t)gy2*Wc + gx;
                            __half v = __float2half_rn(0.0f);
                            if (t1 < Tc)
                                v = g_x[((size_t)((b*Tc + t1)*3 + ch))*HWc + pix];
                            Aout[((size_t)b*HWc + pix)*24 + 21 + ch] = v;
                        }
                    }
                }
            }
            cur ^= 1;
        }

        // ---- Grid barrier between steps (release/acquire via threadfence) ----
        if (t + 1 < Tc) {
            __syncthreads();
            if (tid == 0) {
                __threadfence();
                atomicAdd(&g_bar, 1u);
                const unsigned target = (unsigned)(t + 1) * GRID;
                while (*((volatile unsigned*)&g_bar) < target) { }
                __threadfence();
            }
            __syncthreads();
        }
    }
}

// ===========================================================================
// out[b,h,w,co] = A0[b][pix][co] * mask[pix]
// ===========================================================================
__global__ void mask_out_kernel(const float* __restrict__ mask, float* __restrict__ out) {
    const int n = Bc*HWc*Fc;
    int i = blockIdx.x*blockDim.x + threadIdx.x;
    if (i >= n) return;
    int co   = i % Fc;
    int rest = i / Fc;
    int p    = rest % HWc;
    int b    = rest / HWc;
    out[i] = __half2float(g_A0[((size_t)b*HWc + p)*24 + co]) * mask[p];
}

// ===========================================================================
extern "C" void kernel_launch(void* const* d_in, const int* in_sizes, int n_in,
                              void* d_out, int out_size) {
    const float* x     = (const float*)d_in[0];
    const float* kern  = (const float*)d_in[1];
    const float* rkern = (const float*)d_in[2];
    const float* bias  = (const float*)d_in[3];
    const float* mask  = (const float*)d_in[4];
    float* out = (float*)d_out;
    (void)in_sizes; (void)n_in; (void)out_size;

    cudaFuncSetAttribute(step_all_kernel, cudaFuncAttributeMaxDynamicSharedMemorySize,
                         SMEM_BYTES);

    init_kernel<<<2048, 256>>>(x);
    xsplit_kernel<<<4096, 256>>>(x);
    packB_kernel<<<(88*BROW + 255)/256, 256>>>(kern, rkern);

    step_all_kernel<<<GRID, NTHR, SMEM_BYTES>>>(bias);

    const int n = Bc*HWc*Fc;
    mask_out_kernel<<<(n + 255)/256, 256>>>(mask, out);
}